// round 4
// baseline (speedup 1.0000x reference)
#include <cuda_runtime.h>
#include <cstdint>

#define N_NODES  50000
#define E_EDGES  400000
#define G_GRAPHS 64
#define H_DIM    300
#define L_DIM    100
#define TE       64
#define KC       20
#define ATP      68      // transposed activation pitch (floats per k-row)
#define BPD      260     // duplicated-B pitch (floats per k-row, 128 cols * 2)
#define NTHREADS 256

// Scratch: node features after edge layer 0 / 1 (20 MB each)
__device__ float g_h1[N_NODES * L_DIM];
__device__ float g_h2[N_NODES * L_DIM];

__global__ void zero_kernel(float* __restrict__ p, int n) {
    int i = blockIdx.x * blockDim.x + threadIdx.x;
    int stride = gridDim.x * blockDim.x;
    for (; i < n; i += stride) p[i] = 0.f;
}

// ---- packed fp32x2 helpers (Blackwell FFMA2, PTX-only) ----
__device__ __forceinline__ uint64_t f32x2_fma(uint64_t a, uint64_t b, uint64_t c) {
    uint64_t d;
    asm("fma.rn.f32x2 %0, %1, %2, %3;" : "=l"(d) : "l"(a), "l"(b), "l"(c));
    return d;
}
__device__ __forceinline__ void f32x2_unpack(uint64_t v, float& x, float& y) {
    asm("mov.b64 {%0, %1}, %2;" : "=f"(x), "=f"(y) : "l"(v));
}
__device__ __forceinline__ uint64_t f32x2_pack(float x, float y) {
    uint64_t r;
    asm("mov.b64 %0, {%1, %2};" : "=l"(r) : "f"(x), "f"(y));
    return r;
}

// One [64 x NCOLS] GEMM tile on transposed activations:
//   DsT[c][e] = act( sum_k AsT[k][e] * W[k][c] + bias[c] )
// Thread (cg, ep) owns cols 4cg..4cg+3 x edges 8ep..8ep+7.
// Per k: A = 2x LDS.128 (contiguous edge pairs), B = 2x LDS.128 (duplicated
// (w,w) pairs), 16 FFMA2. Weight chunks double-buffered in smem (1 bar/chunk)
// with register prefetch of the next-next chunk.
template<int KCHUNKS, int KTRUE, int NCOLS, bool RELU, bool TO_GLOBAL>
__device__ __forceinline__ void gemm_tile(
    const float* AsT, const float* __restrict__ W, const float* __restrict__ bias,
    float* DsT, float* s_Bd, const int* s_dst, float* OUT)
{
    const int tid = threadIdx.x;
    const int cg = tid >> 3;   // col-quad 0..31 (cols 4cg..4cg+3)
    const int ep = tid & 7;    // edge octet (edges 8ep..8ep+7)
    constexpr int NB = (NCOLS + 127) / 128;

    const float* Ab = AsT + 8 * ep;

    for (int nb = 0; nb < NB; nb++) {
        const int nbase = nb * 128;
        uint64_t acc[4][4];
#pragma unroll
        for (int p = 0; p < 4; p++)
#pragma unroll
            for (int j = 0; j < 4; j++) acc[p][j] = 0ull;

        float pre[10];   // KC*128/NTHREADS == 10 weight values per thread
        // prefetch chunk 0
#pragma unroll
        for (int r = 0; r < 10; r++) {
            int idx = tid + r * NTHREADS;
            int kk = idx >> 7, c = idx & 127;
            int col = nbase + c;
            pre[r] = (kk < KTRUE && col < NCOLS) ? W[kk * NCOLS + col] : 0.f;
        }
        __syncthreads();   // previous consumers of s_Bd done
#pragma unroll
        for (int r = 0; r < 10; r++) {
            int idx = tid + r * NTHREADS;
            int kk = idx >> 7, c = idx & 127;
            *reinterpret_cast<uint64_t*>(s_Bd + kk * BPD + 2 * c) =
                f32x2_pack(pre[r], pre[r]);
        }
        if (KCHUNKS > 1) {
#pragma unroll
            for (int r = 0; r < 10; r++) {
                int idx = tid + r * NTHREADS;
                int kk = idx >> 7, c = idx & 127;
                int k = KC + kk, col = nbase + c;
                pre[r] = (k < KTRUE && col < NCOLS) ? W[k * NCOLS + col] : 0.f;
            }
        }
        __syncthreads();   // buffer 0 ready

        for (int kc = 0; kc < KCHUNKS; kc++) {
            // stage next chunk into the other buffer (disjoint from current reads)
            if (kc + 1 < KCHUNKS) {
                float* bnx = s_Bd + ((kc + 1) & 1) * (KC * BPD);
#pragma unroll
                for (int r = 0; r < 10; r++) {
                    int idx = tid + r * NTHREADS;
                    int kk = idx >> 7, c = idx & 127;
                    *reinterpret_cast<uint64_t*>(bnx + kk * BPD + 2 * c) =
                        f32x2_pack(pre[r], pre[r]);
                }
                if (kc + 2 < KCHUNKS) {
#pragma unroll
                    for (int r = 0; r < 10; r++) {
                        int idx = tid + r * NTHREADS;
                        int kk = idx >> 7, c = idx & 127;
                        int k = (kc + 2) * KC + kk, col = nbase + c;
                        pre[r] = (k < KTRUE && col < NCOLS) ? W[k * NCOLS + col] : 0.f;
                    }
                }
            }
            const float* Arow = Ab + kc * KC * ATP;
            const float* Brow = s_Bd + (kc & 1) * (KC * BPD) + 8 * cg;
#pragma unroll
            for (int kk = 0; kk < KC; kk++) {
                ulonglong2 al = *reinterpret_cast<const ulonglong2*>(Arow + kk * ATP);
                ulonglong2 ah = *reinterpret_cast<const ulonglong2*>(Arow + kk * ATP + 4);
                ulonglong2 bl = *reinterpret_cast<const ulonglong2*>(Brow + kk * BPD);
                ulonglong2 bh = *reinterpret_cast<const ulonglong2*>(Brow + kk * BPD + 4);
                acc[0][0] = f32x2_fma(al.x, bl.x, acc[0][0]);
                acc[0][1] = f32x2_fma(al.x, bl.y, acc[0][1]);
                acc[0][2] = f32x2_fma(al.x, bh.x, acc[0][2]);
                acc[0][3] = f32x2_fma(al.x, bh.y, acc[0][3]);
                acc[1][0] = f32x2_fma(al.y, bl.x, acc[1][0]);
                acc[1][1] = f32x2_fma(al.y, bl.y, acc[1][1]);
                acc[1][2] = f32x2_fma(al.y, bh.x, acc[1][2]);
                acc[1][3] = f32x2_fma(al.y, bh.y, acc[1][3]);
                acc[2][0] = f32x2_fma(ah.x, bl.x, acc[2][0]);
                acc[2][1] = f32x2_fma(ah.x, bl.y, acc[2][1]);
                acc[2][2] = f32x2_fma(ah.x, bh.x, acc[2][2]);
                acc[2][3] = f32x2_fma(ah.x, bh.y, acc[2][3]);
                acc[3][0] = f32x2_fma(ah.y, bl.x, acc[3][0]);
                acc[3][1] = f32x2_fma(ah.y, bl.y, acc[3][1]);
                acc[3][2] = f32x2_fma(ah.y, bh.x, acc[3][2]);
                acc[3][3] = f32x2_fma(ah.y, bh.y, acc[3][3]);
            }
            __syncthreads();
        }
        // epilogue
#pragma unroll
        for (int j = 0; j < 4; j++) {
            int c = nbase + 4 * cg + j;
            if (c < NCOLS) {
                float bc = bias[c];
                float v[8];
#pragma unroll
                for (int p = 0; p < 4; p++)
                    f32x2_unpack(acc[p][j], v[2 * p], v[2 * p + 1]);
#pragma unroll
                for (int i = 0; i < 8; i++) {
                    v[i] += bc;
                    if (RELU || TO_GLOBAL) v[i] = fmaxf(v[i], 0.f);
                }
                if (TO_GLOBAL) {
                    // relu(segment_max) == atomicMax over clamped msgs into
                    // zero-init buffer; nonneg float order == int order.
#pragma unroll
                    for (int i = 0; i < 8; i++)
                        atomicMax(reinterpret_cast<int*>(OUT) +
                                      s_dst[8 * ep + i] * NCOLS + c,
                                  __float_as_int(v[i]));
                } else {
                    *(float4*)(DsT + c * ATP + 8 * ep) =
                        make_float4(v[0], v[1], v[2], v[3]);
                    *(float4*)(DsT + c * ATP + 8 * ep + 4) =
                        make_float4(v[4], v[5], v[6], v[7]);
                }
            }
        }
    }
}

// Fused per-edge MLP: gather [x_i, x_j - x_i] (transposed) -> 2*CIN -> 300
// -> 300 -> 100 -> clamped scatter-max into OUT[dst].
template<int CIN>
__global__ void __launch_bounds__(NTHREADS, 1)
edge_mlp_kernel(const float* __restrict__ X,
                const int* __restrict__ src, const int* __restrict__ dst,
                const float* __restrict__ W1, const float* __restrict__ B1,
                const float* __restrict__ W2, const float* __restrict__ B2,
                const float* __restrict__ W3, const float* __restrict__ B3,
                float* __restrict__ OUT)
{
    constexpr int KIN  = 2 * CIN;
    constexpr int KCH1 = (KIN + KC - 1) / KC;

    extern __shared__ float smem[];
    float* s_uT  = smem;                    // [300][68] transposed act (in / h2)
    float* s_h1T = smem + H_DIM * ATP;      // [300][68] transposed h1
    float* s_Bd  = smem + 2 * H_DIM * ATP;  // 2 x [KC][260] dup weight chunks
    int* s_src   = (int*)(s_Bd + 2 * KC * BPD);
    int* s_dst   = s_src + TE;

    const int tid = threadIdx.x;
    const int e0  = blockIdx.x * TE;        // grid is exact: 6250*64 == E_EDGES

    if (tid < TE) {
        s_src[tid] = src[e0 + tid];
        s_dst[tid] = dst[e0 + tid];
    }
    __syncthreads();

    // gather transposed: s_uT[k][e] = x_i[k], s_uT[CIN+k][e] = x_j[k]-x_i[k]
    if (CIN % 4 == 0) {
        constexpr int QC = CIN / 4;
        for (int idx = tid; idx < TE * QC; idx += NTHREADS) {
            int e = idx & (TE - 1), kq = idx >> 6;
            float4 xi = *(const float4*)(X + (int64_t)s_dst[e] * CIN + 4 * kq);
            float4 xj = *(const float4*)(X + (int64_t)s_src[e] * CIN + 4 * kq);
            s_uT[(4 * kq + 0) * ATP + e] = xi.x;
            s_uT[(4 * kq + 1) * ATP + e] = xi.y;
            s_uT[(4 * kq + 2) * ATP + e] = xi.z;
            s_uT[(4 * kq + 3) * ATP + e] = xi.w;
            s_uT[(CIN + 4 * kq + 0) * ATP + e] = xj.x - xi.x;
            s_uT[(CIN + 4 * kq + 1) * ATP + e] = xj.y - xi.y;
            s_uT[(CIN + 4 * kq + 2) * ATP + e] = xj.z - xi.z;
            s_uT[(CIN + 4 * kq + 3) * ATP + e] = xj.w - xi.w;
        }
    } else {
        for (int idx = tid; idx < TE * CIN; idx += NTHREADS) {
            int e = idx & (TE - 1), k = idx >> 6;
            float xi = X[(int64_t)s_dst[e] * CIN + k];
            float xj = X[(int64_t)s_src[e] * CIN + k];
            s_uT[k * ATP + e] = xi;
            s_uT[(CIN + k) * ATP + e] = xj - xi;
        }
    }
    // zero the K-pad rows of the input tile (B pad is zero, but garbage smem
    // could be NaN and NaN*0 != 0)
    if (KCH1 * KC > KIN) {
        constexpr int PAD = KCH1 * KC - KIN;
        for (int idx = tid; idx < PAD * TE; idx += NTHREADS) {
            int e = idx & (TE - 1), k = KIN + (idx >> 6);
            s_uT[k * ATP + e] = 0.f;
        }
    }
    // (gemm_tile's leading __syncthreads orders the gather writes)

    gemm_tile<KCH1, KIN, H_DIM, true, false>(s_uT,  W1, B1, s_h1T, s_Bd, s_dst, nullptr);
    gemm_tile<H_DIM / KC, H_DIM, H_DIM, true, false>(s_h1T, W2, B2, s_uT, s_Bd, s_dst, nullptr);
    gemm_tile<H_DIM / KC, H_DIM, L_DIM, false, true>(s_uT,  W3, B3, nullptr, s_Bd, s_dst, OUT);
}

// One block per graph: contiguous segment (batch is sorted) -> add/mean/max
// pooling -> 302 -> 100 -> 100 -> 2 MLP.
__global__ void pool_mlp_kernel(const float* __restrict__ H2,
                                const int* __restrict__ batch,
                                const float* __restrict__ u,
                                const float* __restrict__ w1, const float* __restrict__ b1,
                                const float* __restrict__ w2, const float* __restrict__ b2,
                                const float* __restrict__ w3, const float* __restrict__ b3,
                                float* __restrict__ out)
{
    const int g = blockIdx.x;
    const int t = threadIdx.x;
    __shared__ float p[304];
    __shared__ float q1[100];
    __shared__ float q2[100];

    int s, e2;
    { int a = 0, b = N_NODES; while (a < b) { int m = (a + b) >> 1; if (batch[m] < g) a = m + 1; else b = m; } s = a; }
    { int a = 0, b = N_NODES; while (a < b) { int m = (a + b) >> 1; if (batch[m] < g + 1) a = m + 1; else b = m; } e2 = a; }
    int cnt = e2 - s;

    if (t < L_DIM) {
        float sm = 0.f, mx = 0.f;
        for (int i = s; i < e2; i++) {
            float v = H2[i * L_DIM + t];
            sm += v;
            mx = fmaxf(mx, v);
        }
        p[t] = sm;
        p[L_DIM + t] = sm / fmaxf((float)cnt, 1.0f);
        p[2 * L_DIM + t] = (cnt > 0) ? mx : 0.f;
    }
    if (t < 2) p[3 * L_DIM + t] = u[g * 2 + t];
    __syncthreads();

    if (t < L_DIM) {
        float acc = b1[t];
        for (int k = 0; k < 3 * L_DIM + 2; k++) acc = fmaf(p[k], w1[k * L_DIM + t], acc);
        q1[t] = fmaxf(acc, 0.f);
    }
    __syncthreads();
    if (t < L_DIM) {
        float acc = b2[t];
        for (int k = 0; k < L_DIM; k++) acc = fmaf(q1[k], w2[k * L_DIM + t], acc);
        q2[t] = fmaxf(acc, 0.f);
    }
    __syncthreads();
    if (t < 2) {
        float acc = b3[t];
        for (int k = 0; k < L_DIM; k++) acc = fmaf(q2[k], w3[k * 2 + t], acc);
        out[g * 2 + t] = acc;
    }
}

extern "C" void kernel_launch(void* const* d_in, const int* in_sizes, int n_in,
                              void* d_out, int out_size)
{
    const float* x     = (const float*)d_in[0];
    const int*   ei    = (const int*)d_in[1];
    const int*   batch = (const int*)d_in[2];
    const float* u     = (const float*)d_in[3];
    const float* l0w1  = (const float*)d_in[4];
    const float* l0b1  = (const float*)d_in[5];
    const float* l0w2  = (const float*)d_in[6];
    const float* l0b2  = (const float*)d_in[7];
    const float* l0w3  = (const float*)d_in[8];
    const float* l0b3  = (const float*)d_in[9];
    const float* l1w1  = (const float*)d_in[10];
    const float* l1b1  = (const float*)d_in[11];
    const float* l1w2  = (const float*)d_in[12];
    const float* l1b2  = (const float*)d_in[13];
    const float* l1w3  = (const float*)d_in[14];
    const float* l1b3  = (const float*)d_in[15];
    const float* lw1   = (const float*)d_in[16];
    const float* lb1   = (const float*)d_in[17];
    const float* lw2   = (const float*)d_in[18];
    const float* lb2   = (const float*)d_in[19];
    const float* lw3   = (const float*)d_in[20];
    const float* lb3   = (const float*)d_in[21];
    float* out = (float*)d_out;

    const int* src = ei;
    const int* dst = ei + E_EDGES;

    float *h1p, *h2p;
    cudaGetSymbolAddress((void**)&h1p, g_h1);
    cudaGetSymbolAddress((void**)&h2p, g_h2);

    const int smem_bytes = (2 * H_DIM * ATP + 2 * KC * BPD) * (int)sizeof(float)
                         + 2 * TE * (int)sizeof(int);
    cudaFuncSetAttribute(edge_mlp_kernel<7>,   cudaFuncAttributeMaxDynamicSharedMemorySize, smem_bytes);
    cudaFuncSetAttribute(edge_mlp_kernel<100>, cudaFuncAttributeMaxDynamicSharedMemorySize, smem_bytes);

    zero_kernel<<<304, 256>>>(h1p, N_NODES * L_DIM);
    zero_kernel<<<304, 256>>>(h2p, N_NODES * L_DIM);

    const int nblk = E_EDGES / TE;   // exact
    edge_mlp_kernel<7><<<nblk, NTHREADS, smem_bytes>>>(
        x, src, dst, l0w1, l0b1, l0w2, l0b2, l0w3, l0b3, h1p);
    edge_mlp_kernel<100><<<nblk, NTHREADS, smem_bytes>>>(
        h1p, src, dst, l1w1, l1b1, l1w2, l1b2, l1w3, l1b3, h2p);
    pool_mlp_kernel<<<G_GRAPHS, 128>>>(
        h2p, batch, u, lw1, lb1, lw2, lb2, lw3, lb3, out);
}

// round 5
// speedup vs baseline: 1.8044x; 1.8044x over previous
#include <cuda_runtime.h>
#include <cstdint>

#define N_NODES  50000
#define E_EDGES  400000
#define G_GRAPHS 64
#define H_DIM    300
#define L_DIM    100
#define TE       64
#define KC       30
#define ATP      68      // transposed activation pitch (floats per k-row)
#define BP       132     // B chunk pitch (floats per k-row, 128 cols undup)
#define NTHREADS 256

// Scratch: node features after edge layer 0 / 1 (20 MB each)
__device__ float g_h1[N_NODES * L_DIM];
__device__ float g_h2[N_NODES * L_DIM];

__global__ void zero_kernel(float* __restrict__ p, int n) {
    int i = blockIdx.x * blockDim.x + threadIdx.x;
    int stride = gridDim.x * blockDim.x;
    for (; i < n; i += stride) p[i] = 0.f;
}

// ---- packed fp32x2 helpers (Blackwell FFMA2, PTX-only) ----
__device__ __forceinline__ uint64_t f32x2_fma(uint64_t a, uint64_t b, uint64_t c) {
    uint64_t d;
    asm("fma.rn.f32x2 %0, %1, %2, %3;" : "=l"(d) : "l"(a), "l"(b), "l"(c));
    return d;
}
__device__ __forceinline__ void f32x2_unpack(uint64_t v, float& x, float& y) {
    asm("mov.b64 {%0, %1}, %2;" : "=f"(x), "=f"(y) : "l"(v));
}
__device__ __forceinline__ uint64_t f32x2_pack(float x, float y) {
    uint64_t r;
    asm("mov.b64 %0, {%1, %2};" : "=l"(r) : "f"(x), "f"(y));
    return r;
}
__device__ __forceinline__ uint64_t lds64(const float* p) {
    return *reinterpret_cast<const uint64_t*>(p);
}

// One [64 x NCOLS] GEMM tile on transposed activations:
//   DsT[c][e] = act( sum_k AsT[k][e] * W[k][c] + bias[c] )
// Thread (eq, co) owns edges 4eq..4eq+3 x cols 8co..8co+7.
// Per k: A = 2x LDS.64 (4 edges) duplicated in regs, B = 4x LDS.64 of
// UN-duplicated col-pairs, 16 FFMA2 (f32x2 lane = 2 adjacent cols).
// Weight chunks double-buffered in smem (1 bar/chunk) with reg prefetch.
template<int KCHUNKS, int KTRUE, int NCOLS, bool RELU, bool TO_GLOBAL>
__device__ __forceinline__ void gemm_tile(
    const float* AsT, const float* __restrict__ W, const float* __restrict__ bias,
    float* DsT, float* s_B, const int* s_dst, float* OUT)
{
    const int tid = threadIdx.x;
    const int eq = tid & 15;   // edge quad (edges 4eq..4eq+3)
    const int co = tid >> 4;   // col octet (cols 8co..8co+7)
    constexpr int NB = (NCOLS + 127) / 128;
    constexpr int NPRE = KC * 128 / NTHREADS;   // 15 weight values per thread

    const float* Ab = AsT + 4 * eq;

    for (int nb = 0; nb < NB; nb++) {
        const int nbase = nb * 128;
        uint64_t acc[4][4];
#pragma unroll
        for (int e = 0; e < 4; e++)
#pragma unroll
            for (int j = 0; j < 4; j++) acc[e][j] = 0ull;

        float pre[NPRE];
        // prefetch chunk 0
#pragma unroll
        for (int r = 0; r < NPRE; r++) {
            int idx = tid + r * NTHREADS;
            int kk = idx >> 7, c = idx & 127;
            int col = nbase + c;
            pre[r] = (kk < KTRUE && col < NCOLS) ? W[kk * NCOLS + col] : 0.f;
        }
        __syncthreads();   // previous consumers of s_B done
#pragma unroll
        for (int r = 0; r < NPRE; r++) {
            int idx = tid + r * NTHREADS;
            int kk = idx >> 7, c = idx & 127;
            s_B[kk * BP + c] = pre[r];
        }
        if (KCHUNKS > 1) {
#pragma unroll
            for (int r = 0; r < NPRE; r++) {
                int idx = tid + r * NTHREADS;
                int kk = idx >> 7, c = idx & 127;
                int k = KC + kk, col = nbase + c;
                pre[r] = (k < KTRUE && col < NCOLS) ? W[k * NCOLS + col] : 0.f;
            }
        }
        __syncthreads();   // buffer 0 ready

        for (int kc = 0; kc < KCHUNKS; kc++) {
            // stage next chunk into the other buffer (its last readers finished
            // before the sync that ended iteration kc-1)
            if (kc + 1 < KCHUNKS) {
                float* bnx = s_B + ((kc + 1) & 1) * (KC * BP);
#pragma unroll
                for (int r = 0; r < NPRE; r++) {
                    int idx = tid + r * NTHREADS;
                    int kk = idx >> 7, c = idx & 127;
                    bnx[kk * BP + c] = pre[r];
                }
                if (kc + 2 < KCHUNKS) {
#pragma unroll
                    for (int r = 0; r < NPRE; r++) {
                        int idx = tid + r * NTHREADS;
                        int kk = idx >> 7, c = idx & 127;
                        int k = (kc + 2) * KC + kk, col = nbase + c;
                        pre[r] = (k < KTRUE && col < NCOLS) ? W[k * NCOLS + col] : 0.f;
                    }
                }
            }
            const float* Arow = Ab + kc * KC * ATP;
            const float* Brow = s_B + (kc & 1) * (KC * BP) + 8 * co;
#pragma unroll
            for (int kk = 0; kk < KC; kk++) {
                uint64_t a01 = lds64(Arow + kk * ATP);
                uint64_t a23 = lds64(Arow + kk * ATP + 2);
                float a0, a1, a2, a3;
                f32x2_unpack(a01, a0, a1);
                f32x2_unpack(a23, a2, a3);
                uint64_t ap0 = f32x2_pack(a0, a0);
                uint64_t ap1 = f32x2_pack(a1, a1);
                uint64_t ap2 = f32x2_pack(a2, a2);
                uint64_t ap3 = f32x2_pack(a3, a3);
                uint64_t b0 = lds64(Brow + kk * BP + 0);
                uint64_t b1 = lds64(Brow + kk * BP + 2);
                uint64_t b2 = lds64(Brow + kk * BP + 4);
                uint64_t b3 = lds64(Brow + kk * BP + 6);
                acc[0][0] = f32x2_fma(ap0, b0, acc[0][0]);
                acc[0][1] = f32x2_fma(ap0, b1, acc[0][1]);
                acc[0][2] = f32x2_fma(ap0, b2, acc[0][2]);
                acc[0][3] = f32x2_fma(ap0, b3, acc[0][3]);
                acc[1][0] = f32x2_fma(ap1, b0, acc[1][0]);
                acc[1][1] = f32x2_fma(ap1, b1, acc[1][1]);
                acc[1][2] = f32x2_fma(ap1, b2, acc[1][2]);
                acc[1][3] = f32x2_fma(ap1, b3, acc[1][3]);
                acc[2][0] = f32x2_fma(ap2, b0, acc[2][0]);
                acc[2][1] = f32x2_fma(ap2, b1, acc[2][1]);
                acc[2][2] = f32x2_fma(ap2, b2, acc[2][2]);
                acc[2][3] = f32x2_fma(ap2, b3, acc[2][3]);
                acc[3][0] = f32x2_fma(ap3, b0, acc[3][0]);
                acc[3][1] = f32x2_fma(ap3, b1, acc[3][1]);
                acc[3][2] = f32x2_fma(ap3, b2, acc[3][2]);
                acc[3][3] = f32x2_fma(ap3, b3, acc[3][3]);
            }
            __syncthreads();
        }
        // epilogue: unpack to v[edge][col-within-octet]
        float v[4][8];
#pragma unroll
        for (int e = 0; e < 4; e++)
#pragma unroll
            for (int j = 0; j < 4; j++)
                f32x2_unpack(acc[e][j], v[e][2 * j], v[e][2 * j + 1]);
#pragma unroll
        for (int jj = 0; jj < 8; jj++) {
            int c = nbase + 8 * co + jj;
            if (c < NCOLS) {
                float bc = bias[c];
                float w0 = v[0][jj] + bc, w1 = v[1][jj] + bc;
                float w2 = v[2][jj] + bc, w3 = v[3][jj] + bc;
                if (RELU || TO_GLOBAL) {
                    w0 = fmaxf(w0, 0.f); w1 = fmaxf(w1, 0.f);
                    w2 = fmaxf(w2, 0.f); w3 = fmaxf(w3, 0.f);
                }
                if (TO_GLOBAL) {
                    // relu(segment_max) == atomicMax over clamped msgs into
                    // zero-init buffer; nonneg float order == int order.
                    int* o = reinterpret_cast<int*>(OUT);
                    atomicMax(o + s_dst[4 * eq + 0] * NCOLS + c, __float_as_int(w0));
                    atomicMax(o + s_dst[4 * eq + 1] * NCOLS + c, __float_as_int(w1));
                    atomicMax(o + s_dst[4 * eq + 2] * NCOLS + c, __float_as_int(w2));
                    atomicMax(o + s_dst[4 * eq + 3] * NCOLS + c, __float_as_int(w3));
                } else {
                    float* D = DsT + c * ATP + 4 * eq;
                    *reinterpret_cast<uint64_t*>(D)     = f32x2_pack(w0, w1);
                    *reinterpret_cast<uint64_t*>(D + 2) = f32x2_pack(w2, w3);
                }
            }
        }
    }
}

// Fused per-edge MLP: gather [x_i, x_j - x_i] (transposed) -> 2*CIN -> 300
// -> 300 -> 100 -> clamped scatter-max into OUT[dst].
template<int CIN>
__global__ void __launch_bounds__(NTHREADS, 1)
edge_mlp_kernel(const float* __restrict__ X,
                const int* __restrict__ src, const int* __restrict__ dst,
                const float* __restrict__ W1, const float* __restrict__ B1,
                const float* __restrict__ W2, const float* __restrict__ B2,
                const float* __restrict__ W3, const float* __restrict__ B3,
                float* __restrict__ OUT)
{
    constexpr int KIN  = 2 * CIN;
    constexpr int KCH1 = (KIN + KC - 1) / KC;

    extern __shared__ float smem[];
    float* s_uT  = smem;                    // [300][68] transposed act (in / h2)
    float* s_h1T = smem + H_DIM * ATP;      // [300][68] transposed h1
    float* s_B   = smem + 2 * H_DIM * ATP;  // 2 x [KC][132] weight chunks
    int* s_src   = (int*)(s_B + 2 * KC * BP);
    int* s_dst   = s_src + TE;

    const int tid = threadIdx.x;
    const int e0  = blockIdx.x * TE;        // grid is exact: 6250*64 == E_EDGES

    if (tid < TE) {
        s_src[tid] = src[e0 + tid];
        s_dst[tid] = dst[e0 + tid];
    }
    __syncthreads();

    // gather transposed: s_uT[k][e] = x_i[k], s_uT[CIN+k][e] = x_j[k]-x_i[k]
    if (CIN % 4 == 0) {
        constexpr int QC = CIN / 4;
        for (int idx = tid; idx < TE * QC; idx += NTHREADS) {
            int e = idx & (TE - 1), kq = idx >> 6;
            float4 xi = *(const float4*)(X + (int64_t)s_dst[e] * CIN + 4 * kq);
            float4 xj = *(const float4*)(X + (int64_t)s_src[e] * CIN + 4 * kq);
            s_uT[(4 * kq + 0) * ATP + e] = xi.x;
            s_uT[(4 * kq + 1) * ATP + e] = xi.y;
            s_uT[(4 * kq + 2) * ATP + e] = xi.z;
            s_uT[(4 * kq + 3) * ATP + e] = xi.w;
            s_uT[(CIN + 4 * kq + 0) * ATP + e] = xj.x - xi.x;
            s_uT[(CIN + 4 * kq + 1) * ATP + e] = xj.y - xi.y;
            s_uT[(CIN + 4 * kq + 2) * ATP + e] = xj.z - xi.z;
            s_uT[(CIN + 4 * kq + 3) * ATP + e] = xj.w - xi.w;
        }
    } else {
        for (int idx = tid; idx < TE * CIN; idx += NTHREADS) {
            int e = idx & (TE - 1), k = idx >> 6;
            float xi = X[(int64_t)s_dst[e] * CIN + k];
            float xj = X[(int64_t)s_src[e] * CIN + k];
            s_uT[k * ATP + e] = xi;
            s_uT[(CIN + k) * ATP + e] = xj - xi;
        }
    }
    // zero the K-pad rows of the input tile (B pad is zero, but garbage smem
    // could be NaN and NaN*0 != 0)
    if (KCH1 * KC > KIN) {
        constexpr int PAD = KCH1 * KC - KIN;
        for (int idx = tid; idx < PAD * TE; idx += NTHREADS) {
            int e = idx & (TE - 1), k = KIN + (idx >> 6);
            s_uT[k * ATP + e] = 0.f;
        }
    }
    // (gemm_tile's leading __syncthreads orders the gather writes)

    gemm_tile<KCH1, KIN, H_DIM, true, false>(s_uT,  W1, B1, s_h1T, s_B, s_dst, nullptr);
    gemm_tile<(H_DIM + KC - 1) / KC, H_DIM, H_DIM, true, false>(s_h1T, W2, B2, s_uT, s_B, s_dst, nullptr);
    gemm_tile<(H_DIM + KC - 1) / KC, H_DIM, L_DIM, false, true>(s_uT,  W3, B3, nullptr, s_B, s_dst, OUT);
}

// One block per graph: contiguous segment (batch is sorted) -> add/mean/max
// pooling -> 302 -> 100 -> 100 -> 2 MLP.
__global__ void pool_mlp_kernel(const float* __restrict__ H2,
                                const int* __restrict__ batch,
                                const float* __restrict__ u,
                                const float* __restrict__ w1, const float* __restrict__ b1,
                                const float* __restrict__ w2, const float* __restrict__ b2,
                                const float* __restrict__ w3, const float* __restrict__ b3,
                                float* __restrict__ out)
{
    const int g = blockIdx.x;
    const int t = threadIdx.x;
    __shared__ float p[304];
    __shared__ float q1[100];
    __shared__ float q2[100];

    int s, e2;
    { int a = 0, b = N_NODES; while (a < b) { int m = (a + b) >> 1; if (batch[m] < g) a = m + 1; else b = m; } s = a; }
    { int a = 0, b = N_NODES; while (a < b) { int m = (a + b) >> 1; if (batch[m] < g + 1) a = m + 1; else b = m; } e2 = a; }
    int cnt = e2 - s;

    if (t < L_DIM) {
        float sm = 0.f, mx = 0.f;
        for (int i = s; i < e2; i++) {
            float v = H2[i * L_DIM + t];
            sm += v;
            mx = fmaxf(mx, v);
        }
        p[t] = sm;
        p[L_DIM + t] = sm / fmaxf((float)cnt, 1.0f);
        p[2 * L_DIM + t] = (cnt > 0) ? mx : 0.f;
    }
    if (t < 2) p[3 * L_DIM + t] = u[g * 2 + t];
    __syncthreads();

    if (t < L_DIM) {
        float acc = b1[t];
        for (int k = 0; k < 3 * L_DIM + 2; k++) acc = fmaf(p[k], w1[k * L_DIM + t], acc);
        q1[t] = fmaxf(acc, 0.f);
    }
    __syncthreads();
    if (t < L_DIM) {
        float acc = b2[t];
        for (int k = 0; k < L_DIM; k++) acc = fmaf(q1[k], w2[k * L_DIM + t], acc);
        q2[t] = fmaxf(acc, 0.f);
    }
    __syncthreads();
    if (t < 2) {
        float acc = b3[t];
        for (int k = 0; k < L_DIM; k++) acc = fmaf(q2[k], w3[k * 2 + t], acc);
        out[g * 2 + t] = acc;
    }
}

extern "C" void kernel_launch(void* const* d_in, const int* in_sizes, int n_in,
                              void* d_out, int out_size)
{
    const float* x     = (const float*)d_in[0];
    const int*   ei    = (const int*)d_in[1];
    const int*   batch = (const int*)d_in[2];
    const float* u     = (const float*)d_in[3];
    const float* l0w1  = (const float*)d_in[4];
    const float* l0b1  = (const float*)d_in[5];
    const float* l0w2  = (const float*)d_in[6];
    const float* l0b2  = (const float*)d_in[7];
    const float* l0w3  = (const float*)d_in[8];
    const float* l0b3  = (const float*)d_in[9];
    const float* l1w1  = (const float*)d_in[10];
    const float* l1b1  = (const float*)d_in[11];
    const float* l1w2  = (const float*)d_in[12];
    const float* l1b2  = (const float*)d_in[13];
    const float* l1w3  = (const float*)d_in[14];
    const float* l1b3  = (const float*)d_in[15];
    const float* lw1   = (const float*)d_in[16];
    const float* lb1   = (const float*)d_in[17];
    const float* lw2   = (const float*)d_in[18];
    const float* lb2   = (const float*)d_in[19];
    const float* lw3   = (const float*)d_in[20];
    const float* lb3   = (const float*)d_in[21];
    float* out = (float*)d_out;

    const int* src = ei;
    const int* dst = ei + E_EDGES;

    float *h1p, *h2p;
    cudaGetSymbolAddress((void**)&h1p, g_h1);
    cudaGetSymbolAddress((void**)&h2p, g_h2);

    const int smem_bytes = (2 * H_DIM * ATP + 2 * KC * BP) * (int)sizeof(float)
                         + 2 * TE * (int)sizeof(int);
    cudaFuncSetAttribute(edge_mlp_kernel<7>,   cudaFuncAttributeMaxDynamicSharedMemorySize, smem_bytes);
    cudaFuncSetAttribute(edge_mlp_kernel<100>, cudaFuncAttributeMaxDynamicSharedMemorySize, smem_bytes);

    zero_kernel<<<304, 256>>>(h1p, N_NODES * L_DIM);
    zero_kernel<<<304, 256>>>(h2p, N_NODES * L_DIM);

    const int nblk = E_EDGES / TE;   // exact
    edge_mlp_kernel<7><<<nblk, NTHREADS, smem_bytes>>>(
        x, src, dst, l0w1, l0b1, l0w2, l0b2, l0w3, l0b3, h1p);
    edge_mlp_kernel<100><<<nblk, NTHREADS, smem_bytes>>>(
        h1p, src, dst, l1w1, l1b1, l1w2, l1b2, l1w3, l1b3, h2p);
    pool_mlp_kernel<<<G_GRAPHS, 128>>>(
        h2p, batch, u, lw1, lb1, lw2, lb2, lw3, lb3, out);
}